// round 3
// baseline (speedup 1.0000x reference)
#include <cuda_runtime.h>
#include <cfloat>
#include <cstdint>

// Problem constants (fixed by the reference setup_inputs)
#define NTEST   16384
#define NTRAIN  16384
#define DIM     192
#define NCLASS  2
#define KNN     5

#define TM      128     // test rows per CTA
#define TN      64      // train cols per tile
#define NTHREADS 256    // 16 (trow) x 16 (tcol); each thread: 8 rows x 4 cols

__device__ float g_ynorm[NTRAIN];

// ---------------------------------------------------------------------------
// Kernel 1: train-row squared norms (one warp per row, coalesced)
// ---------------------------------------------------------------------------
__global__ void ynorm_kernel(const float* __restrict__ Htrain) {
    int gwarp = (blockIdx.x * blockDim.x + threadIdx.x) >> 5;
    int lane  = threadIdx.x & 31;
    if (gwarp >= NTRAIN) return;
    const float* row = Htrain + (size_t)gwarp * DIM;
    float s = 0.f;
    #pragma unroll
    for (int k = lane; k < DIM; k += 32) { float v = row[k]; s += v * v; }
    #pragma unroll
    for (int o = 16; o; o >>= 1) s += __shfl_xor_sync(0xffffffffu, s, o);
    if (lane == 0) g_ynorm[gwarp] = s;
}

// ---------------------------------------------------------------------------
// Packed f32x2 helpers (Blackwell sm_100+)
// ---------------------------------------------------------------------------
__device__ __forceinline__ unsigned long long splat_f32x2(float v) {
    unsigned long long r;
    asm("mov.b64 %0, {%1, %1};" : "=l"(r) : "f"(v));
    return r;
}
__device__ __forceinline__ void fma_f32x2(unsigned long long& acc,
                                          unsigned long long a,
                                          unsigned long long b) {
    asm("fma.rn.f32x2 %0, %1, %2, %0;" : "+l"(acc) : "l"(a), "l"(b));
}
__device__ __forceinline__ float2 unpack_f32x2(unsigned long long v) {
    float lo, hi;
    asm("mov.b64 {%0, %1}, %2;" : "=f"(lo), "=f"(hi) : "l"(v));
    return make_float2(lo, hi);
}

// ---------------------------------------------------------------------------
// Kernel 2: fused distance-GEMM + streaming top-5 + gather/mean
//
// SMEM layout (floats):
//   As   [DIM][TM]        24576   (A block resident for whole CTA)
//   Bs   [DIM][TN+1]      12480   (stride 65 -> conflict-free k-major writes)
//   bufd [TM][TN]          8192   candidate distances
//   bufi [TM][TN]          8192   candidate indices
//   top5d[TM][5]            640
//   top5i[TM][5]            640
//   thr  [TM]               128
//   cnt  [TM]               128
//   yns  [TN]                64
// total 55048 floats = 220192 B  (< 227 KB opt-in)
// ---------------------------------------------------------------------------
#define SM_AS     0
#define SM_BS     (SM_AS + DIM * TM)            // 24576
#define SM_BUFD   (SM_BS + DIM * (TN + 1))      // 24576+12480
#define SM_BUFI   (SM_BUFD + TM * TN)
#define SM_T5D    (SM_BUFI + TM * TN)
#define SM_T5I    (SM_T5D + TM * KNN)
#define SM_THR    (SM_T5I + TM * KNN)
#define SM_CNT    (SM_THR + TM)
#define SM_YNS    (SM_CNT + TM)
#define SM_TOTALF (SM_YNS + TN)

__global__ __launch_bounds__(NTHREADS, 1)
void knn_fused_kernel(const float* __restrict__ Htest,
                      const float* __restrict__ Htrain,
                      const float* __restrict__ phat,
                      float* __restrict__ out) {
    extern __shared__ float smem[];
    float* As    = smem + SM_AS;
    float* Bs    = smem + SM_BS;
    float* bufd  = smem + SM_BUFD;
    int*   bufi  = (int*)(smem + SM_BUFI);
    float* top5d = smem + SM_T5D;
    int*   top5i = (int*)(smem + SM_T5I);
    float* thr   = smem + SM_THR;
    int*   cnt   = (int*)(smem + SM_CNT);
    float* yns   = smem + SM_YNS;

    const int tid  = threadIdx.x;
    const int trow = tid & 15;   // 0..15 -> 8 rows each
    const int tcol = tid >> 4;   // 0..15 -> 4 cols each
    const int m0   = blockIdx.x * TM;

    // ---- init per-row state ----
    if (tid < TM) {
        thr[tid] = FLT_MAX;
        cnt[tid] = 0;
        #pragma unroll
        for (int i = 0; i < KNN; i++) {
            top5d[tid * KNN + i] = FLT_MAX;
            top5i[tid * KNN + i] = 0;
        }
    }

    // ---- load A block (128 test rows, full DIM) once ----
    for (int e = tid; e < TM * DIM; e += NTHREADS) {
        int k = e % DIM;
        int m = e / DIM;
        As[k * TM + m] = Htest[(size_t)(m0 + m) * DIM + k];
    }
    __syncthreads();

    const float* aBase = As + trow * 8;
    const float* bBase = Bs + tcol * 4;

    // ---- stream over train tiles ----
    for (int jt = 0; jt < NTRAIN; jt += TN) {
        // load B tile [DIM][TN] k-major, stride TN+1 => conflict-free
        for (int e = tid; e < TN * DIM; e += NTHREADS) {
            int k = e % DIM;
            int j = e / DIM;
            Bs[k * (TN + 1) + j] = Htrain[(size_t)(jt + j) * DIM + k];
        }
        if (tid < TN) yns[tid] = g_ynorm[jt + tid];
        __syncthreads();

        // ---- compute 128x64 dot block; acc pairs along rows (f32x2) ----
        unsigned long long acc[4][4];
        #pragma unroll
        for (int r = 0; r < 4; r++)
            #pragma unroll
            for (int c = 0; c < 4; c++) acc[r][c] = 0ull;

        #pragma unroll 4
        for (int k = 0; k < DIM; k++) {
            const float* ak = aBase + k * TM;
            ulonglong2 aLo = *(const ulonglong2*)(ak);       // row pairs (0,1),(2,3)
            ulonglong2 aHi = *(const ulonglong2*)(ak + 4);   // row pairs (4,5),(6,7)
            const float* bk = bBase + k * (TN + 1);
            unsigned long long b0 = splat_f32x2(bk[0]);
            unsigned long long b1 = splat_f32x2(bk[1]);
            unsigned long long b2 = splat_f32x2(bk[2]);
            unsigned long long b3 = splat_f32x2(bk[3]);
            fma_f32x2(acc[0][0], aLo.x, b0); fma_f32x2(acc[0][1], aLo.x, b1);
            fma_f32x2(acc[0][2], aLo.x, b2); fma_f32x2(acc[0][3], aLo.x, b3);
            fma_f32x2(acc[1][0], aLo.y, b0); fma_f32x2(acc[1][1], aLo.y, b1);
            fma_f32x2(acc[1][2], aLo.y, b2); fma_f32x2(acc[1][3], aLo.y, b3);
            fma_f32x2(acc[2][0], aHi.x, b0); fma_f32x2(acc[2][1], aHi.x, b1);
            fma_f32x2(acc[2][2], aHi.x, b2); fma_f32x2(acc[2][3], aHi.x, b3);
            fma_f32x2(acc[3][0], aHi.y, b0); fma_f32x2(acc[3][1], aHi.y, b1);
            fma_f32x2(acc[3][2], aHi.y, b2); fma_f32x2(acc[3][3], aHi.y, b3);
        }

        // ---- insert candidates that beat the per-row threshold ----
        #pragma unroll
        for (int rp = 0; rp < 4; rp++) {
            int r0 = trow * 8 + rp * 2;
            float th0 = thr[r0];
            float th1 = thr[r0 + 1];
            #pragma unroll
            for (int c = 0; c < 4; c++) {
                float2 v = unpack_f32x2(acc[rp][c]);
                int col = tcol * 4 + c;
                float yn = yns[col];
                int gcol = jt + col;
                float d0 = yn - 2.0f * v.x;
                float d1 = yn - 2.0f * v.y;
                if (d0 < th0) {
                    int p = atomicAdd(&cnt[r0], 1);
                    if (p < TN) { bufd[r0 * TN + p] = d0; bufi[r0 * TN + p] = gcol; }
                }
                if (d1 < th1) {
                    int p = atomicAdd(&cnt[r0 + 1], 1);
                    if (p < TN) { bufd[(r0 + 1) * TN + p] = d1; bufi[(r0 + 1) * TN + p] = gcol; }
                }
            }
        }
        __syncthreads();

        // ---- compact: one thread per test row merges its buffer into top-5 ----
        if (tid < TM) {
            int c = cnt[tid];
            if (c > 0) {
                if (c > TN) c = TN;
                float dd[KNN]; int ii[KNN];
                #pragma unroll
                for (int i = 0; i < KNN; i++) { dd[i] = top5d[tid*KNN+i]; ii[i] = top5i[tid*KNN+i]; }
                for (int i = 0; i < c; i++) {
                    float d = bufd[tid * TN + i];
                    if (d < dd[KNN - 1]) {
                        int idx = bufi[tid * TN + i];
                        int j = KNN - 1;
                        #pragma unroll
                        for (int q = KNN - 1; q > 0; q--) {
                            if (j > 0 && dd[j - 1] > d) { dd[j] = dd[j-1]; ii[j] = ii[j-1]; j--; }
                        }
                        dd[j] = d; ii[j] = idx;
                    }
                }
                #pragma unroll
                for (int i = 0; i < KNN; i++) { top5d[tid*KNN+i] = dd[i]; top5i[tid*KNN+i] = ii[i]; }
                thr[tid] = dd[KNN - 1];
                cnt[tid] = 0;
            }
        }
        __syncthreads();
    }

    // ---- epilogue: gather p_hat over top-5, mean, write [NCLASS, NTEST] ----
    if (tid < TM) {
        int row = m0 + tid;
        float s0 = 0.f, s1 = 0.f;
        #pragma unroll
        for (int i = 0; i < KNN; i++) {
            int idx = top5i[tid * KNN + i];
            s0 += phat[idx];
            s1 += phat[NTRAIN + idx];
        }
        out[row]          = s0 * (1.0f / KNN);
        out[NTEST + row]  = s1 * (1.0f / KNN);
    }
}

// ---------------------------------------------------------------------------
extern "C" void kernel_launch(void* const* d_in, const int* in_sizes, int n_in,
                              void* d_out, int out_size) {
    const float* Htest  = (const float*)d_in[0];
    const float* Htrain = (const float*)d_in[1];
    const float* phat   = (const float*)d_in[2];
    // d_in[3] is K (=5, fixed by the problem); not readable without sync.
    float* out = (float*)d_out;

    // y-norm pre-pass: one warp per train row
    {
        int threads = 256;
        int blocks = (NTRAIN * 32 + threads - 1) / threads;
        ynorm_kernel<<<blocks, threads>>>(Htrain);
    }

    // fused GEMM + top-5 + gather (cudaFuncSetAttribute is idempotent and
    // capture-legal: it is not a stream operation)
    size_t smem_bytes = (size_t)SM_TOTALF * sizeof(float);
    cudaFuncSetAttribute(knn_fused_kernel,
                         cudaFuncAttributeMaxDynamicSharedMemorySize,
                         (int)smem_bytes);
    knn_fused_kernel<<<NTEST / TM, NTHREADS, smem_bytes>>>(Htest, Htrain, phat, out);
}

// round 6
// speedup vs baseline: 3.5330x; 3.5330x over previous
#include <cuda_runtime.h>
#include <cuda_bf16.h>
#include <cfloat>
#include <cstdint>

// ---------------------------------------------------------------------------
// Problem constants
// ---------------------------------------------------------------------------
#define NTEST   16384
#define NTRAIN  16384
#define DIM     192
#define NCLASS  2
#define KNN     5

#define TM      128                 // test rows per CTA
#define TN      128                 // train cols per tile
#define NTILES  (NTRAIN / TN)       // 128
#define KSTEPS  (DIM / 16)          // 12 mma k-steps
#define NTHREADS 256                // 8 warps: 2 (M) x 4 (N), warp tile 64x32
#define NCAND   16                  // approx top-16 kept per row
#define NCAP    48                  // candidate buffer depth per row

#define ROWSTRIDE 200               // bf16 elems per smem row (400B: conflict-free ldmatrix)

// ---------------------------------------------------------------------------
// Global scratch (no cudaMalloc allowed)
// ---------------------------------------------------------------------------
__device__ float         g_ynorm[NTRAIN];
__device__ __nv_bfloat16 g_Abf[NTEST * DIM];
__device__ __nv_bfloat16 g_Bbf[NTRAIN * DIM];

// ---------------------------------------------------------------------------
// PTX helpers (all base-ISA: legal on sm_100 without 'a')
// ---------------------------------------------------------------------------
__device__ __forceinline__ uint32_t smem_u32(const void* p) {
    uint32_t a;
    asm("{ .reg .u64 t; cvta.to.shared.u64 t, %1; cvt.u32.u64 %0, t; }"
        : "=r"(a) : "l"(p));
    return a;
}

#define CP_ASYNC16(dst, src) \
    asm volatile("cp.async.cg.shared.global [%0], [%1], 16;" :: "r"(dst), "l"(src))
#define CP_COMMIT() asm volatile("cp.async.commit_group;" ::: "memory")
#define CP_WAIT0()  asm volatile("cp.async.wait_group 0;" ::: "memory")
#define CP_WAIT1()  asm volatile("cp.async.wait_group 1;" ::: "memory")

#define LDMATRIX_X4(r0, r1, r2, r3, addr) \
    asm volatile("ldmatrix.sync.aligned.m8n8.x4.shared.b16 {%0,%1,%2,%3}, [%4];" \
                 : "=r"(r0), "=r"(r1), "=r"(r2), "=r"(r3) : "r"(addr))

__device__ __forceinline__ void mma_bf16(float* c,
                                         uint32_t a0, uint32_t a1, uint32_t a2, uint32_t a3,
                                         uint32_t b0, uint32_t b1) {
    asm volatile("mma.sync.aligned.m16n8k16.row.col.f32.bf16.bf16.f32 "
                 "{%0,%1,%2,%3}, {%4,%5,%6,%7}, {%8,%9}, {%0,%1,%2,%3};"
                 : "+f"(c[0]), "+f"(c[1]), "+f"(c[2]), "+f"(c[3])
                 : "r"(a0), "r"(a1), "r"(a2), "r"(a3), "r"(b0), "r"(b1));
}

// ---------------------------------------------------------------------------
// SMEM layout (bytes)
// ---------------------------------------------------------------------------
#define TILE_BYTES   (TM * ROWSTRIDE * 2)    // 51200
#define OFF_A        0
#define OFF_B        51200                   // two buffers: +0 / +51200
#define OFF_YNS      153600                  // float [2][128]
#define OFF_THR      154624                  // float [128]
#define OFF_CNT      155136                  // int   [128]
#define OFF_BUFD     155648                  // float [128][NCAP]
#define OFF_BUFI     180224                  // int   [128][NCAP]
#define OFF_T16D     204800                  // float [128][16]
#define OFF_T16I     212992                  // int   [128][16]
#define SMEM_BYTES   221184

// load a 128x192 bf16 tile into padded smem via cp.async (24 x 16B per row)
__device__ __forceinline__ void tile_load_async(uint32_t sdst, const __nv_bfloat16* src,
                                                int tid) {
    #pragma unroll
    for (int it = 0; it < 12; it++) {
        int g  = tid + it * NTHREADS;        // 0..3071
        int r  = g / 24;
        int ch = g % 24;
        uint32_t dst = sdst + r * (ROWSTRIDE * 2) + ch * 16;
        const char* s = (const char*)(src + (size_t)r * DIM) + ch * 16;
        CP_ASYNC16(dst, s);
    }
}

// ---------------------------------------------------------------------------
// Prep kernels
// ---------------------------------------------------------------------------
__global__ void ynorm_kernel(const float* __restrict__ Htrain) {
    int gwarp = (blockIdx.x * blockDim.x + threadIdx.x) >> 5;
    int lane  = threadIdx.x & 31;
    if (gwarp >= NTRAIN) return;
    const float* row = Htrain + (size_t)gwarp * DIM;
    float s = 0.f;
    #pragma unroll
    for (int k = lane; k < DIM; k += 32) { float v = row[k]; s += v * v; }
    #pragma unroll
    for (int o = 16; o; o >>= 1) s += __shfl_xor_sync(0xffffffffu, s, o);
    if (lane == 0) g_ynorm[gwarp] = s;
}

__global__ void convert_kernel(const float* __restrict__ Htest,
                               const float* __restrict__ Htrain) {
    int total = NTEST * DIM;
    for (int i = blockIdx.x * blockDim.x + threadIdx.x; i < total;
         i += gridDim.x * blockDim.x) {
        g_Abf[i] = __float2bfloat16(Htest[i]);
        g_Bbf[i] = __float2bfloat16(Htrain[i]);
    }
}

// ---------------------------------------------------------------------------
// Main kernel: bf16 mma.sync GEMM -> streaming top-16 -> exact fp32 re-rank
// ---------------------------------------------------------------------------
__global__ __launch_bounds__(NTHREADS, 1)
void knn_mma_kernel(const float* __restrict__ Htest,
                    const float* __restrict__ Htrain,
                    const float* __restrict__ phat,
                    float* __restrict__ out) {
    extern __shared__ __align__(1024) char smem[];
    const uint32_t sbase = smem_u32(smem);
    const int tid   = threadIdx.x;
    const int wid   = tid >> 5;
    const int lid   = tid & 31;
    const int warpM = wid >> 2;      // 0..1 -> rows warpM*64..+63
    const int warpN = wid & 3;       // 0..3 -> cols warpN*32..+31
    const int m0    = blockIdx.x * TM;

    float* yns   = (float*)(smem + OFF_YNS);
    float* thr   = (float*)(smem + OFF_THR);
    int*   cnt   = (int*)  (smem + OFF_CNT);
    float* bufd  = (float*)(smem + OFF_BUFD);
    int*   bufi  = (int*)  (smem + OFF_BUFI);
    float* t16d  = (float*)(smem + OFF_T16D);
    int*   t16i  = (int*)  (smem + OFF_T16I);

    // ---- prologue: A tile + B tile 0 via cp.async ----
    tile_load_async(sbase + OFF_A, g_Abf + (size_t)m0 * DIM, tid);
    tile_load_async(sbase + OFF_B, g_Bbf, tid);
    CP_COMMIT();

    if (tid < TM) {
        thr[tid] = FLT_MAX;
        cnt[tid] = 0;
        #pragma unroll
        for (int i = 0; i < NCAND; i++) {
            t16d[tid * NCAND + i] = FLT_MAX;
            t16i[tid * NCAND + i] = 0;
        }
    }
    CP_WAIT0();
    __syncthreads();

    // ldmatrix lane addressing: row = (lid&15), k-halfword chunk = (lid>>4)
    const int lrow   = lid & 15;
    const int lchunk = lid >> 4;
    uint32_t a_addr[4];
    #pragma unroll
    for (int mf = 0; mf < 4; mf++)
        a_addr[mf] = sbase + OFF_A +
                     (warpM * 64 + mf * 16 + lrow) * (ROWSTRIDE * 2) + lchunk * 16;

    const int erow0 = warpM * 64 + (lid >> 2);   // +mf*16, +8 in epilogue
    const int ecol0 = warpN * 32 + 2 * (lid & 3);

    // ---- main loop over B tiles ----
    for (int jt = 0; jt < NTILES; jt++) {
        const int cur = jt & 1;

        if (jt + 1 < NTILES)
            tile_load_async(sbase + OFF_B + (1 - cur) * TILE_BYTES,
                            g_Bbf + (size_t)(jt + 1) * TN * DIM, tid);
        CP_COMMIT();
        if (tid < TM) yns[cur * TM + tid] = g_ynorm[jt * TN + tid];
        CP_WAIT1();          // current B tile resident
        __syncthreads();

        // ---- 128x128x192 bf16 mma ----
        float acc[4][4][4];
        #pragma unroll
        for (int mf = 0; mf < 4; mf++)
            #pragma unroll
            for (int nf = 0; nf < 4; nf++)
                #pragma unroll
                for (int q = 0; q < 4; q++) acc[mf][nf][q] = 0.f;

        uint32_t b_addr0 = sbase + OFF_B + cur * TILE_BYTES +
                           (warpN * 32 + lrow) * (ROWSTRIDE * 2) + lchunk * 16;
        uint32_t b_addr1 = b_addr0 + 16 * (ROWSTRIDE * 2);

        #pragma unroll
        for (int ks = 0; ks < KSTEPS; ks++) {
            const uint32_t ka = ks * 32;
            uint32_t a[4][4], b[2][4];
            #pragma unroll
            for (int mf = 0; mf < 4; mf++)
                LDMATRIX_X4(a[mf][0], a[mf][1], a[mf][2], a[mf][3], a_addr[mf] + ka);
            LDMATRIX_X4(b[0][0], b[0][1], b[0][2], b[0][3], b_addr0 + ka);
            LDMATRIX_X4(b[1][0], b[1][1], b[1][2], b[1][3], b_addr1 + ka);
            #pragma unroll
            for (int mf = 0; mf < 4; mf++)
                #pragma unroll
                for (int nf = 0; nf < 4; nf++)
                    mma_bf16(acc[mf][nf],
                             a[mf][0], a[mf][1], a[mf][2], a[mf][3],
                             b[nf >> 1][nf & 1], b[nf >> 1][2 + (nf & 1)]);
        }

        // ---- epilogue: 4 chunks of 32 columns; threshold-insert + compact ----
        const float* yn = yns + cur * TM;
        const int colbase = jt * TN;
        #pragma unroll
        for (int c = 0; c < 4; c++) {
            const int col0 = ecol0 + c * 8;        // within tile
            const int col1 = col0 + 1;
            const float y0 = yn[col0];
            const float y1 = yn[col1];
            #pragma unroll
            for (int mf = 0; mf < 4; mf++) {
                const float* cc = acc[mf][c];
                const int r0 = erow0 + mf * 16;
                const int r1 = r0 + 8;
                float d00 = fmaf(-2.f, cc[0], y0);
                float d01 = fmaf(-2.f, cc[1], y1);
                float d10 = fmaf(-2.f, cc[2], y0);
                float d11 = fmaf(-2.f, cc[3], y1);
                if (d00 < thr[r0]) {
                    int p = atomicAdd(&cnt[r0], 1);
                    if (p < NCAP) { bufd[r0*NCAP+p] = d00; bufi[r0*NCAP+p] = colbase+col0; }
                }
                if (d01 < thr[r0]) {
                    int p = atomicAdd(&cnt[r0], 1);
                    if (p < NCAP) { bufd[r0*NCAP+p] = d01; bufi[r0*NCAP+p] = colbase+col1; }
                }
                if (d10 < thr[r1]) {
                    int p = atomicAdd(&cnt[r1], 1);
                    if (p < NCAP) { bufd[r1*NCAP+p] = d10; bufi[r1*NCAP+p] = colbase+col0; }
                }
                if (d11 < thr[r1]) {
                    int p = atomicAdd(&cnt[r1], 1);
                    if (p < NCAP) { bufd[r1*NCAP+p] = d11; bufi[r1*NCAP+p] = colbase+col1; }
                }
            }
            __syncthreads();
            // compact: one thread per row merges buffer into smem top-16
            if (tid < TM) {
                int cn = cnt[tid];
                if (cn > 0) {
                    if (cn > NCAP) cn = NCAP;
                    float* td = t16d + tid * NCAND;
                    int*   ti = t16i + tid * NCAND;
                    for (int i = 0; i < cn; i++) {
                        float d = bufd[tid * NCAP + i];
                        if (d < td[NCAND - 1]) {
                            int idx = bufi[tid * NCAP + i];
                            int j = NCAND - 1;
                            while (j > 0 && td[j - 1] > d) {
                                td[j] = td[j - 1]; ti[j] = ti[j - 1]; j--;
                            }
                            td[j] = d; ti[j] = idx;
                        }
                    }
                    thr[tid] = td[NCAND - 1];
                    cnt[tid] = 0;
                }
            }
            __syncthreads();
        }
    }

    // ---- exact fp32 re-rank: warp per row, 16 candidates each ----
    for (int r = wid; r < TM; r += 8) {
        const int rowg = m0 + r;
        const float* xrow = Htest + (size_t)rowg * DIM;
        float xv[6];
        #pragma unroll
        for (int j = 0; j < 6; j++) xv[j] = xrow[lid + 32 * j];

        float bd[KNN]; int bi[KNN];
        #pragma unroll
        for (int i = 0; i < KNN; i++) { bd[i] = FLT_MAX; bi[i] = 0x7fffffff; }

        for (int c = 0; c < NCAND; c++) {
            int idx = t16i[r * NCAND + c];
            const float* trow = Htrain + (size_t)idx * DIM;
            float s = 0.f;
            #pragma unroll
            for (int j = 0; j < 6; j++) s = fmaf(xv[j], trow[lid + 32 * j], s);
            #pragma unroll
            for (int o = 16; o; o >>= 1) s += __shfl_xor_sync(0xffffffffu, s, o);
            if (lid == 0) {
                float d = g_ynorm[idx] - 2.0f * s;
                int j = KNN;
                while (j > 0 && (d < bd[j - 1] ||
                                 (d == bd[j - 1] && idx < bi[j - 1]))) j--;
                if (j < KNN) {
                    for (int q = KNN - 1; q > j; q--) { bd[q] = bd[q-1]; bi[q] = bi[q-1]; }
                    bd[j] = d; bi[j] = idx;
                }
            }
        }
        if (lid == 0) {
            float s0 = 0.f, s1 = 0.f;
            #pragma unroll
            for (int i = 0; i < KNN; i++) {
                int idx = bi[i];
                s0 += phat[idx];
                s1 += phat[NTRAIN + idx];
            }
            out[rowg]         = s0 * (1.0f / KNN);
            out[NTEST + rowg] = s1 * (1.0f / KNN);
        }
    }
}

// ---------------------------------------------------------------------------
extern "C" void kernel_launch(void* const* d_in, const int* in_sizes, int n_in,
                              void* d_out, int out_size) {
    const float* Htest  = (const float*)d_in[0];
    const float* Htrain = (const float*)d_in[1];
    const float* phat   = (const float*)d_in[2];
    float* out = (float*)d_out;

    {
        int threads = 256;
        int blocks  = (NTRAIN * 32 + threads - 1) / threads;
        ynorm_kernel<<<blocks, threads>>>(Htrain);
    }
    convert_kernel<<<1024, 256>>>(Htest, Htrain);

    cudaFuncSetAttribute(knn_mma_kernel,
                         cudaFuncAttributeMaxDynamicSharedMemorySize, SMEM_BYTES);
    knn_mma_kernel<<<NTEST / TM, NTHREADS, SMEM_BYTES>>>(Htest, Htrain, phat, out);
}

// round 7
// speedup vs baseline: 4.1492x; 1.1744x over previous
#include <cuda_runtime.h>
#include <cuda_bf16.h>
#include <cfloat>
#include <cstdint>

// ---------------------------------------------------------------------------
// Problem constants
// ---------------------------------------------------------------------------
#define NTEST   16384
#define NTRAIN  16384
#define DIM     192
#define NCLASS  2
#define KNN     5

#define TM      128                 // test rows per CTA
#define TN      128                 // train cols per tile
#define NTILES  (NTRAIN / TN)       // 128
#define KSTEPS  (DIM / 16)          // 12 mma k-steps
#define NTHREADS 256                // 8 warps: 4 (M) x 2 (N), warp tile 32x64
#define NCAND   16                  // approx top-16 kept per row
#define NCAP    64                  // candidate buffer depth (== max inserts per half)

#define ROWSTRIDE 200               // bf16 elems per smem row (400B: conflict-free ldmatrix)

// ---------------------------------------------------------------------------
// Global scratch (no cudaMalloc allowed)
// ---------------------------------------------------------------------------
__device__ float         g_ynorm[NTRAIN];
__device__ __nv_bfloat16 g_Abf[NTEST * DIM];
__device__ __nv_bfloat16 g_Bbf[NTRAIN * DIM];

// ---------------------------------------------------------------------------
// PTX helpers (base ISA, legal on sm_100)
// ---------------------------------------------------------------------------
__device__ __forceinline__ uint32_t smem_u32(const void* p) {
    uint32_t a;
    asm("{ .reg .u64 t; cvta.to.shared.u64 t, %1; cvt.u32.u64 %0, t; }"
        : "=r"(a) : "l"(p));
    return a;
}

#define CP_ASYNC16(dst, src) \
    asm volatile("cp.async.cg.shared.global [%0], [%1], 16;" :: "r"(dst), "l"(src))
#define CP_COMMIT() asm volatile("cp.async.commit_group;" ::: "memory")
#define CP_WAIT0()  asm volatile("cp.async.wait_group 0;" ::: "memory")
#define CP_WAIT1()  asm volatile("cp.async.wait_group 1;" ::: "memory")

#define LDMATRIX_X4(r0, r1, r2, r3, addr) \
    asm volatile("ldmatrix.sync.aligned.m8n8.x4.shared.b16 {%0,%1,%2,%3}, [%4];" \
                 : "=r"(r0), "=r"(r1), "=r"(r2), "=r"(r3) : "r"(addr))

__device__ __forceinline__ void mma_bf16(float* c,
                                         uint32_t a0, uint32_t a1, uint32_t a2, uint32_t a3,
                                         uint32_t b0, uint32_t b1) {
    asm volatile("mma.sync.aligned.m16n8k16.row.col.f32.bf16.bf16.f32 "
                 "{%0,%1,%2,%3}, {%4,%5,%6,%7}, {%8,%9}, {%0,%1,%2,%3};"
                 : "+f"(c[0]), "+f"(c[1]), "+f"(c[2]), "+f"(c[3])
                 : "r"(a0), "r"(a1), "r"(a2), "r"(a3), "r"(b0), "r"(b1));
}

// ---------------------------------------------------------------------------
// SMEM layout (bytes). A staging region overlaps the candidate buffers:
// A is consumed into registers in the prologue, buffers used only afterwards.
// ---------------------------------------------------------------------------
#define TILE_BYTES   (TM * ROWSTRIDE * 2)    // 51200
#define OFF_B        0                       // two buffers: +0 / +51200
#define OFF_YNS      102400                  // float [2][128]
#define OFF_THR      103424                  // float [128]
#define OFF_CNT      103936                  // int   [128]
#define OFF_T16D     104448                  // float [128][16]
#define OFF_T16I     112640                  // int   [128][16]
#define OFF_BUFD     120832                  // float [128][NCAP]  (32768)
#define OFF_BUFI     153600                  // int   [128][NCAP]  (32768)
#define OFF_A        120832                  // A staging overlaps BUFD/BUFI
#define SMEM_BYTES   186368

// load a 128x192 bf16 tile into padded smem via cp.async (24 x 16B per row)
__device__ __forceinline__ void tile_load_async(uint32_t sdst, const __nv_bfloat16* src,
                                                int tid) {
    #pragma unroll
    for (int it = 0; it < 12; it++) {
        int g  = tid + it * NTHREADS;        // 0..3071
        int r  = g / 24;
        int ch = g % 24;
        uint32_t dst = sdst + r * (ROWSTRIDE * 2) + ch * 16;
        const char* s = (const char*)(src + (size_t)r * DIM) + ch * 16;
        CP_ASYNC16(dst, s);
    }
}

// ---------------------------------------------------------------------------
// Prep kernels
// ---------------------------------------------------------------------------
__global__ void ynorm_kernel(const float* __restrict__ Htrain) {
    int gwarp = (blockIdx.x * blockDim.x + threadIdx.x) >> 5;
    int lane  = threadIdx.x & 31;
    if (gwarp >= NTRAIN) return;
    const float* row = Htrain + (size_t)gwarp * DIM;
    float s = 0.f;
    #pragma unroll
    for (int k = lane; k < DIM; k += 32) { float v = row[k]; s += v * v; }
    #pragma unroll
    for (int o = 16; o; o >>= 1) s += __shfl_xor_sync(0xffffffffu, s, o);
    if (lane == 0) g_ynorm[gwarp] = s;
}

__global__ void convert_kernel(const float* __restrict__ Htest,
                               const float* __restrict__ Htrain) {
    int total = NTEST * DIM / 2;
    for (int i = blockIdx.x * blockDim.x + threadIdx.x; i < total;
         i += gridDim.x * blockDim.x) {
        float2 a = ((const float2*)Htest)[i];
        float2 b = ((const float2*)Htrain)[i];
        ((__nv_bfloat162*)g_Abf)[i] = __floats2bfloat162_rn(a.x, a.y);
        ((__nv_bfloat162*)g_Bbf)[i] = __floats2bfloat162_rn(b.x, b.y);
    }
}

// ---------------------------------------------------------------------------
// Main kernel: bf16 mma.sync GEMM (A register-resident) -> top-16 -> fp32 re-rank
// ---------------------------------------------------------------------------
__global__ __launch_bounds__(NTHREADS, 1)
void knn_mma_kernel(const float* __restrict__ Htest,
                    const float* __restrict__ Htrain,
                    const float* __restrict__ phat,
                    float* __restrict__ out) {
    extern __shared__ __align__(1024) char smem[];
    const uint32_t sbase = smem_u32(smem);
    const int tid   = threadIdx.x;
    const int wid   = tid >> 5;
    const int lid   = tid & 31;
    const int warpM = wid & 3;       // 0..3 -> rows warpM*32..+31
    const int warpN = wid >> 2;      // 0..1 -> cols warpN*64..+63
    const int m0    = blockIdx.x * TM;

    float* yns   = (float*)(smem + OFF_YNS);
    float* thr   = (float*)(smem + OFF_THR);
    int*   cnt   = (int*)  (smem + OFF_CNT);
    float* bufd  = (float*)(smem + OFF_BUFD);
    int*   bufi  = (int*)  (smem + OFF_BUFI);
    float* t16d  = (float*)(smem + OFF_T16D);
    int*   t16i  = (int*)  (smem + OFF_T16I);

    // ---- prologue: stage A + B0 via cp.async ----
    tile_load_async(sbase + OFF_A, g_Abf + (size_t)m0 * DIM, tid);
    tile_load_async(sbase + OFF_B, g_Bbf, tid);
    CP_COMMIT();

    if (tid < TM) {
        thr[tid] = FLT_MAX;
        cnt[tid] = 0;
        #pragma unroll
        for (int i = 0; i < NCAND; i++) {
            t16d[tid * NCAND + i] = FLT_MAX;
            t16i[tid * NCAND + i] = 0;
        }
    }
    CP_WAIT0();
    __syncthreads();

    // ---- load A fragments into registers ONCE (A fixed for whole CTA) ----
    const int lrow   = lid & 15;
    const int lchunk = lid >> 4;
    uint32_t afrag[2][KSTEPS][4];
    #pragma unroll
    for (int mf = 0; mf < 2; mf++) {
        uint32_t base = sbase + OFF_A +
                        (warpM * 32 + mf * 16 + lrow) * (ROWSTRIDE * 2) + lchunk * 16;
        #pragma unroll
        for (int ks = 0; ks < KSTEPS; ks++)
            LDMATRIX_X4(afrag[mf][ks][0], afrag[mf][ks][1],
                        afrag[mf][ks][2], afrag[mf][ks][3], base + ks * 32);
    }
    // A staging region is dead from here on; buffers may reuse it after the
    // next __syncthreads() (first one inside the main loop).

    const int erow0 = warpM * 32 + (lid >> 2);
    const int ecol0 = warpN * 64 + 2 * (lid & 3);

    // ---- main loop over B tiles ----
    for (int jt = 0; jt < NTILES; jt++) {
        const int cur = jt & 1;

        if (jt + 1 < NTILES)
            tile_load_async(sbase + OFF_B + (1 - cur) * TILE_BYTES,
                            g_Bbf + (size_t)(jt + 1) * TN * DIM, tid);
        CP_COMMIT();
        if (tid < TM) yns[cur * TM + tid] = g_ynorm[jt * TN + tid];
        CP_WAIT1();          // current B tile resident
        __syncthreads();

        // ---- 128x128x192: B from smem, A from registers ----
        float acc[2][8][4];
        #pragma unroll
        for (int mf = 0; mf < 2; mf++)
            #pragma unroll
            for (int nf = 0; nf < 8; nf++)
                #pragma unroll
                for (int q = 0; q < 4; q++) acc[mf][nf][q] = 0.f;

        uint32_t b_base = sbase + OFF_B + cur * TILE_BYTES +
                          (warpN * 64 + lrow) * (ROWSTRIDE * 2) + lchunk * 16;

        #pragma unroll
        for (int ks = 0; ks < KSTEPS; ks++) {
            const uint32_t ka = ks * 32;
            uint32_t b[4][4];
            #pragma unroll
            for (int g = 0; g < 4; g++)
                LDMATRIX_X4(b[g][0], b[g][1], b[g][2], b[g][3],
                            b_base + g * 16 * (ROWSTRIDE * 2) + ka);
            #pragma unroll
            for (int mf = 0; mf < 2; mf++)
                #pragma unroll
                for (int nf = 0; nf < 8; nf++)
                    mma_bf16(acc[mf][nf],
                             afrag[mf][ks][0], afrag[mf][ks][1],
                             afrag[mf][ks][2], afrag[mf][ks][3],
                             b[nf >> 1][nf & 1], b[nf >> 1][2 + (nf & 1)]);
        }

        // ---- epilogue: 2 halves of 64 columns/row (inserts <= NCAP bounded) ----
        const float* yn = yns + cur * TM;
        const int colbase = jt * TN;
        #pragma unroll
        for (int half = 0; half < 2; half++) {
            #pragma unroll
            for (int nfh = 0; nfh < 4; nfh++) {
                const int nf   = half * 4 + nfh;
                const int col0 = ecol0 + nf * 8;
                const int col1 = col0 + 1;
                const float y0 = yn[col0];
                const float y1 = yn[col1];
                #pragma unroll
                for (int mf = 0; mf < 2; mf++) {
                    const float* cc = acc[mf][nf];
                    const int r0 = erow0 + mf * 16;
                    const int r1 = r0 + 8;
                    float d00 = fmaf(-2.f, cc[0], y0);
                    float d01 = fmaf(-2.f, cc[1], y1);
                    float d10 = fmaf(-2.f, cc[2], y0);
                    float d11 = fmaf(-2.f, cc[3], y1);
                    if (d00 < thr[r0]) {
                        int p = atomicAdd(&cnt[r0], 1);
                        bufd[r0*NCAP+p] = d00; bufi[r0*NCAP+p] = colbase+col0;
                    }
                    if (d01 < thr[r0]) {
                        int p = atomicAdd(&cnt[r0], 1);
                        bufd[r0*NCAP+p] = d01; bufi[r0*NCAP+p] = colbase+col1;
                    }
                    if (d10 < thr[r1]) {
                        int p = atomicAdd(&cnt[r1], 1);
                        bufd[r1*NCAP+p] = d10; bufi[r1*NCAP+p] = colbase+col0;
                    }
                    if (d11 < thr[r1]) {
                        int p = atomicAdd(&cnt[r1], 1);
                        bufd[r1*NCAP+p] = d11; bufi[r1*NCAP+p] = colbase+col1;
                    }
                }
            }
            __syncthreads();
            // compact: one thread per row merges its buffer into smem top-16
            if (tid < TM) {
                int cn = cnt[tid];
                if (cn > 0) {
                    float* td = t16d + tid * NCAND;
                    int*   ti = t16i + tid * NCAND;
                    for (int i = 0; i < cn; i++) {
                        float d = bufd[tid * NCAP + i];
                        if (d < td[NCAND - 1]) {
                            int idx = bufi[tid * NCAP + i];
                            int j = NCAND - 1;
                            while (j > 0 && td[j - 1] > d) {
                                td[j] = td[j - 1]; ti[j] = ti[j - 1]; j--;
                            }
                            td[j] = d; ti[j] = idx;
                        }
                    }
                    thr[tid] = td[NCAND - 1];
                    cnt[tid] = 0;
                }
            }
            __syncthreads();
        }
    }

    // ---- exact fp32 re-rank: warp per row, 16 candidates each ----
    for (int r = wid; r < TM; r += 8) {
        const int rowg = m0 + r;
        const float* xrow = Htest + (size_t)rowg * DIM;
        float xv[6];
        #pragma unroll
        for (int j = 0; j < 6; j++) xv[j] = xrow[lid + 32 * j];

        float bd[KNN]; int bi[KNN];
        #pragma unroll
        for (int i = 0; i < KNN; i++) { bd[i] = FLT_MAX; bi[i] = 0x7fffffff; }

        for (int c = 0; c < NCAND; c++) {
            int idx = t16i[r * NCAND + c];
            const float* trow = Htrain + (size_t)idx * DIM;
            float s = 0.f;
            #pragma unroll
            for (int j = 0; j < 6; j++) s = fmaf(xv[j], trow[lid + 32 * j], s);
            #pragma unroll
            for (int o = 16; o; o >>= 1) s += __shfl_xor_sync(0xffffffffu, s, o);
            if (lid == 0) {
                float d = g_ynorm[idx] - 2.0f * s;
                int j = KNN;
                while (j > 0 && (d < bd[j - 1] ||
                                 (d == bd[j - 1] && idx < bi[j - 1]))) j--;
                if (j < KNN) {
                    for (int q = KNN - 1; q > j; q--) { bd[q] = bd[q-1]; bi[q] = bi[q-1]; }
                    bd[j] = d; bi[j] = idx;
                }
            }
        }
        if (lid == 0) {
            float s0 = 0.f, s1 = 0.f;
            #pragma unroll
            for (int i = 0; i < KNN; i++) {
                int idx = bi[i];
                s0 += phat[idx];
                s1 += phat[NTRAIN + idx];
            }
            out[rowg]         = s0 * (1.0f / KNN);
            out[NTEST + rowg] = s1 * (1.0f / KNN);
        }
    }
}

// ---------------------------------------------------------------------------
extern "C" void kernel_launch(void* const* d_in, const int* in_sizes, int n_in,
                              void* d_out, int out_size) {
    const float* Htest  = (const float*)d_in[0];
    const float* Htrain = (const float*)d_in[1];
    const float* phat   = (const float*)d_in[2];
    float* out = (float*)d_out;

    {
        int threads = 256;
        int blocks  = (NTRAIN * 32 + threads - 1) / threads;
        ynorm_kernel<<<blocks, threads>>>(Htrain);
    }
    convert_kernel<<<1024, 256>>>(Htest, Htrain);

    cudaFuncSetAttribute(knn_mma_kernel,
                         cudaFuncAttributeMaxDynamicSharedMemorySize, SMEM_BYTES);
    knn_mma_kernel<<<NTEST / TM, NTHREADS, SMEM_BYTES>>>(Htest, Htrain, phat, out);
}